// round 12
// baseline (speedup 1.0000x reference)
#include <cuda_runtime.h>
#include <cuda_fp16.h>
#include <cstdint>
#include <cstddef>

// ============================================================
// GAT attention head, N=8192, IN_F=128, OUT_F=64
//  h = X@W ; e = LeakyReLU(fs_i + fd_j) masked by adj ; softmax ; P@h ; elu
//
// exp(LR(fs+fd)) = max(E_i*E_j, G_i*G_j) -> no exp in N^2 loop.
// Fixed-max softmax -> single pass; fp16 P/h via mma.sync.m16n8k16.
//
// PERSISTENT: 296 CTAs own static contiguous ranges of 8192 tiles
// (64 row-blocks x 128 j-tiles of 64) -> 98.9% utilization; flush by
// atomicAdd on row-block change.
// WARP TILING M=32 x j-split 2: each B-fragment LDS feeds 2 MMAs ->
// H smem read traffic halved (crossbar was the binding resource).
// ============================================================

#define NT 8192
#define IN_FEAT 128
#define OUT_FEAT 64
#define JTILE 64
#define TOTAL_TILES 8192
#define WORKERS 296
#define ADJROW 320               // 64*4 + 64 pad: LDS.128 conflict-free
#define HROW 160                 // 64*2 + 32 pad: LDS.64 conflict-free

#define ADJ_BYTES (128 * ADJROW)         // 40960
#define H_BYTES   (OUT_FEAT * HROW)      // 10240
#define EG_BYTES  (JTILE * 8)            // 512
#define OFF_ADJ(i) ((i) * ADJ_BYTES)
#define OFF_H(i)   (2 * ADJ_BYTES + (i) * H_BYTES)
#define OFF_EG(i)  (2 * ADJ_BYTES + 2 * H_BYTES + (i) * EG_BYTES)
#define ATTN_SMEM  (2 * ADJ_BYTES + 2 * H_BYTES + 2 * EG_BYTES)  // 103424

#define PREP_WS   0
#define PREP_XS   (IN_FEAT * OUT_FEAT * 4)
#define PREP_HS   (PREP_XS + 32 * IN_FEAT * 4)
#define HS_STRIDE 34
#define PREP_SMEM (PREP_HS + OUT_FEAT * HS_STRIDE * 2)

// ---------------- scratch (static device arrays; no allocation) ----------
__device__ __half g_ht[OUT_FEAT * NT];
__device__ float2 g_EGs[NT];
__device__ float2 g_EGd[NT];
__device__ float  g_num[NT * OUT_FEAT];
__device__ float  g_den[NT];

// ---------------- helpers ------------------------------------------------
__device__ __forceinline__ uint32_t smem_u32(const void* p) {
    uint32_t a;
    asm("{ .reg .u64 t; cvta.to.shared.u64 t, %1; cvt.u32.u64 %0, t; }"
        : "=r"(a) : "l"(p));
    return a;
}
__device__ __forceinline__ void cp16(uint32_t dst, const void* src) {
    asm volatile("cp.async.cg.shared.global [%0], [%1], 16;" :: "r"(dst), "l"(src));
}
__device__ __forceinline__ void cp8(uint32_t dst, const void* src) {
    asm volatile("cp.async.ca.shared.global [%0], [%1], 8;" :: "r"(dst), "l"(src));
}
#define CP_COMMIT() asm volatile("cp.async.commit_group;" ::: "memory")
#define CP_WAIT(n)  asm volatile("cp.async.wait_group %0;" :: "n"(n) : "memory")

__device__ __forceinline__ void mma16816(float* d, uint32_t a0, uint32_t a1,
                                         uint32_t a2, uint32_t a3,
                                         uint32_t b0, uint32_t b1) {
    asm volatile(
        "mma.sync.aligned.m16n8k16.row.col.f32.f16.f16.f32 "
        "{%0,%1,%2,%3}, {%4,%5,%6,%7}, {%8,%9}, {%0,%1,%2,%3};"
        : "+f"(d[0]), "+f"(d[1]), "+f"(d[2]), "+f"(d[3])
        : "r"(a0), "r"(a1), "r"(a2), "r"(a3), "r"(b0), "r"(b1));
}
__device__ __forceinline__ uint32_t packh2(float x, float y) {
    __half2 h = __floats2half2_rn(x, y);
    return *reinterpret_cast<uint32_t*>(&h);
}

// =========================================================================
// Kernel 0: zero accumulators
// =========================================================================
__global__ void __launch_bounds__(256) zero_kernel() {
    int gid = blockIdx.x * 256 + threadIdx.x;
    ((float4*)g_num)[gid] = make_float4(0.f, 0.f, 0.f, 0.f);
    if (gid < NT / 4)
        ((float4*)g_den)[gid] = make_float4(0.f, 0.f, 0.f, 0.f);
}

// =========================================================================
// Kernel 1: h = X@W ; EG tables ; h^T fp16 (coalesced via smem transpose).
// 256 blocks x 512 threads; warp owns 2 rows.
// =========================================================================
__global__ void __launch_bounds__(512) prep_kernel(const float* __restrict__ x,
                                                   const float* __restrict__ W,
                                                   const float* __restrict__ a) {
    extern __shared__ __align__(16) char sm[];
    float*  Ws = (float*)(sm + PREP_WS);
    float*  xs = (float*)(sm + PREP_XS);
    __half* hs = (__half*)(sm + PREP_HS);

    int tid = threadIdx.x;
    int i0 = blockIdx.x * 32;

    {
        const float4* W4 = (const float4*)W;
        float4* Ws4 = (float4*)Ws;
#pragma unroll
        for (int u = 0; u < 4; u++) Ws4[tid + u * 512] = W4[tid + u * 512];
        const float4* x4 = (const float4*)(x + (size_t)i0 * IN_FEAT);
        float4* xs4 = (float4*)xs;
#pragma unroll
        for (int u = 0; u < 2; u++) xs4[tid + u * 512] = x4[tid + u * 512];
    }
    __syncthreads();

    int w = tid >> 5, l = tid & 31;
    float acc[2][2];
#pragma unroll
    for (int rr = 0; rr < 2; rr++) { acc[rr][0] = 0.f; acc[rr][1] = 0.f; }

#pragma unroll 4
    for (int k4 = 0; k4 < IN_FEAT; k4 += 4) {
        float2 wv[4];
#pragma unroll
        for (int kk = 0; kk < 4; kk++)
            wv[kk] = *(const float2*)&Ws[(k4 + kk) * OUT_FEAT + 2 * l];
#pragma unroll
        for (int rr = 0; rr < 2; rr++) {
            float4 xv = *(const float4*)&xs[(w * 2 + rr) * IN_FEAT + k4];
            acc[rr][0] = fmaf(xv.x, wv[0].x, acc[rr][0]);
            acc[rr][1] = fmaf(xv.x, wv[0].y, acc[rr][1]);
            acc[rr][0] = fmaf(xv.y, wv[1].x, acc[rr][0]);
            acc[rr][1] = fmaf(xv.y, wv[1].y, acc[rr][1]);
            acc[rr][0] = fmaf(xv.z, wv[2].x, acc[rr][0]);
            acc[rr][1] = fmaf(xv.z, wv[2].y, acc[rr][1]);
            acc[rr][0] = fmaf(xv.w, wv[3].x, acc[rr][0]);
            acc[rr][1] = fmaf(xv.w, wv[3].y, acc[rr][1]);
        }
    }

#pragma unroll
    for (int rr = 0; rr < 2; rr++) {
        int il = w * 2 + rr;
        hs[(2 * l) * HS_STRIDE + il]     = __float2half(acc[rr][0]);
        hs[(2 * l + 1) * HS_STRIDE + il] = __float2half(acc[rr][1]);
    }

    float a0 = a[2 * l], a1 = a[2 * l + 1];
    float a2 = a[OUT_FEAT + 2 * l], a3 = a[OUT_FEAT + 2 * l + 1];
#pragma unroll
    for (int rr = 0; rr < 2; rr++) {
        float s = acc[rr][0] * a0 + acc[rr][1] * a1;
        float d = acc[rr][0] * a2 + acc[rr][1] * a3;
#pragma unroll
        for (int off = 16; off; off >>= 1) {
            s += __shfl_xor_sync(0xFFFFFFFFu, s, off);
            d += __shfl_xor_sync(0xFFFFFFFFu, d, off);
        }
        if (l == 0) {
            int i = i0 + w * 2 + rr;
            g_EGs[i] = make_float2(expf(s), expf(0.2f * s));
            g_EGd[i] = make_float2(expf(d), expf(0.2f * d));
        }
    }
    __syncthreads();

#pragma unroll
    for (int u = 0; u < 2; u++) {
        int id = tid + u * 512;
        int f = id >> 4, c = id & 15;
        uint32_t v = *(const uint32_t*)&hs[f * HS_STRIDE + 2 * c];
        *(uint32_t*)&g_ht[(size_t)f * NT + i0 + 2 * c] = v;
    }
}

// =========================================================================
// Kernel 2: persistent fused attention. 296 CTAs x 256 thr, 2 CTAs/SM.
// Warp = (row-group wg 0..3) x (j-half jh 0..1): 32 rows x 64 feats,
// contraction span 32 j. B-fragment shared by 2 m-tiles.
// =========================================================================
__global__ void __launch_bounds__(256, 2) attn_kernel(const int* __restrict__ adj) {
    extern __shared__ __align__(16) char sm[];
    uint32_t sb = smem_u32(sm);

    int tid = threadIdx.x, w = tid >> 5, lane = tid & 31;
    int wg = w >> 1, jh = w & 1;
    int r = lane >> 2, q = lane & 3;
    int cta = blockIdx.x;

    int t0 = (int)(((long long)cta * TOTAL_TILES) / WORKERS);
    int t1 = (int)(((long long)(cta + 1) * TOTAL_TILES) / WORKERS);

    float acc[2][8][4];
#pragma unroll
    for (int mt = 0; mt < 2; mt++)
#pragma unroll
        for (int nt = 0; nt < 8; nt++)
#pragma unroll
            for (int v = 0; v < 4; v++) acc[mt][nt][v] = 0.f;
    float ds[4] = {0.f, 0.f, 0.f, 0.f};   // rows r, r+8, r+16, r+24

    auto issue_tile = [&](int buf, int t) {
        int i0t = (t >> 7) * 128;
        int j0t = (t & 127) * JTILE;
        uint32_t ab = sb + OFF_ADJ(buf);
        uint32_t hb = sb + OFF_H(buf);
        uint32_t eb = sb + OFF_EG(buf);
#pragma unroll
        for (int u = 0; u < 8; u++) {
            int id = tid + u * 256;
            int row = id >> 4, c = id & 15;
            cp16(ab + row * ADJROW + c * 16,
                 &adj[(size_t)(i0t + row) * NT + j0t + c * 4]);
        }
#pragma unroll
        for (int u = 0; u < 2; u++) {
            int id = tid + u * 256;
            int f = id >> 3, c = id & 7;
            cp16(hb + f * HROW + c * 16,
                 &g_ht[(size_t)f * NT + j0t + c * 8]);
        }
        if (tid < JTILE) cp8(eb + tid * 8, &g_EGd[j0t + tid]);
        CP_COMMIT();
    };

    int cur_rb = t0 >> 7;
    float2 egs[4];
#pragma unroll
    for (int m = 0; m < 4; m++) egs[m] = g_EGs[cur_rb * 128 + wg * 32 + m * 8 + r];

    auto flush = [&](int rb) {
#pragma unroll
        for (int mt = 0; mt < 2; mt++) {
            float d0 = ds[mt * 2], d1 = ds[mt * 2 + 1];
            d0 += __shfl_xor_sync(0xFFFFFFFFu, d0, 1);
            d0 += __shfl_xor_sync(0xFFFFFFFFu, d0, 2);
            d1 += __shfl_xor_sync(0xFFFFFFFFu, d1, 1);
            d1 += __shfl_xor_sync(0xFFFFFFFFu, d1, 2);
            int R = rb * 128 + wg * 32 + mt * 16 + r;
            if (q == 0) {
                atomicAdd(&g_den[R], d0);
                atomicAdd(&g_den[R + 8], d1);
            }
#pragma unroll
            for (int nt = 0; nt < 8; nt++) {
                int col = nt * 8 + q * 2;
                atomicAdd(&g_num[(size_t)R * OUT_FEAT + col],           acc[mt][nt][0]);
                atomicAdd(&g_num[(size_t)R * OUT_FEAT + col + 1],       acc[mt][nt][1]);
                atomicAdd(&g_num[(size_t)(R + 8) * OUT_FEAT + col],     acc[mt][nt][2]);
                atomicAdd(&g_num[(size_t)(R + 8) * OUT_FEAT + col + 1], acc[mt][nt][3]);
                acc[mt][nt][0] = acc[mt][nt][1] = acc[mt][nt][2] = acc[mt][nt][3] = 0.f;
            }
            ds[mt * 2] = 0.f; ds[mt * 2 + 1] = 0.f;
        }
    };

    issue_tile(t0 & 1, t0);

    for (int t = t0; t < t1; t++) {
        int b = t & 1;
        __syncthreads();
        if (t + 1 < t1) { issue_tile((t + 1) & 1, t + 1); CP_WAIT(1); }
        else            { CP_WAIT(0); }
        __syncthreads();

        int rb = t >> 7;
        if (rb != cur_rb) {
            flush(cur_rb);
            cur_rb = rb;
#pragma unroll
            for (int m = 0; m < 4; m++) egs[m] = g_EGs[rb * 128 + wg * 32 + m * 8 + r];
        }

        const char* ab = sm + OFF_ADJ(b);
        const char* hb = sm + OFF_H(b);
        const float2* eb = (const float2*)(sm + OFF_EG(b));

#pragma unroll
        for (int kk = 0; kk < 2; kk++) {
            int colb = jh * 128 + kk * 64 + q * 16;     // adj byte column
            int rbase = wg * 32 + r;
            int4 av0 = *(const int4*)(ab + (rbase)      * ADJROW + colb);
            int4 av1 = *(const int4*)(ab + (rbase + 8)  * ADJROW + colb);
            int4 av2 = *(const int4*)(ab + (rbase + 16) * ADJROW + colb);
            int4 av3 = *(const int4*)(ab + (rbase + 24) * ADJROW + colb);
            int jloc = jh * 32 + kk * 16 + 4 * q;
            float4 egA = *(const float4*)&eb[jloc];     // E,G: j, j+1
            float4 egB = *(const float4*)&eb[jloc + 2]; // E,G: j+2, j+3

            float p[4][4];
            const int4* avp[4] = {&av0, &av1, &av2, &av3};
#pragma unroll
            for (int m = 0; m < 4; m++) {
                float E = egs[m].x, G = egs[m].y;
                p[m][0] = avp[m]->x ? fmaxf(E * egA.x, G * egA.y) : 0.f;
                p[m][1] = avp[m]->y ? fmaxf(E * egA.z, G * egA.w) : 0.f;
                p[m][2] = avp[m]->z ? fmaxf(E * egB.x, G * egB.y) : 0.f;
                p[m][3] = avp[m]->w ? fmaxf(E * egB.z, G * egB.w) : 0.f;
                ds[m] += (p[m][0] + p[m][1]) + (p[m][2] + p[m][3]);
            }

            // A-frags: sigma maps k=2q,2q+1 -> j=4q,4q+1 ; k=2q+8,2q+9 -> j=4q+2,4q+3
            uint32_t A0 = packh2(p[0][0], p[0][1]);
            uint32_t A1 = packh2(p[1][0], p[1][1]);
            uint32_t A2 = packh2(p[0][2], p[0][3]);
            uint32_t A3 = packh2(p[1][2], p[1][3]);
            uint32_t C0 = packh2(p[2][0], p[2][1]);
            uint32_t C1 = packh2(p[3][0], p[3][1]);
            uint32_t C2 = packh2(p[2][2], p[2][3]);
            uint32_t C3 = packh2(p[3][2], p[3][3]);

            int ko = jh * 64 + kk * 32 + q * 8;
#pragma unroll
            for (int nt = 0; nt < 8; nt++) {
                uint2 bb = *(const uint2*)(hb + (nt * 8 + r) * HROW + ko);
                mma16816(acc[0][nt], A0, A1, A2, A3, bb.x, bb.y);
                mma16816(acc[1][nt], C0, C1, C2, C3, bb.x, bb.y);
            }
        }
    }

    flush(cur_rb);
}

// =========================================================================
// Kernel 3: divide + elu (vectorized)
// =========================================================================
__global__ void __launch_bounds__(256) finalize_kernel(float* __restrict__ out) {
    int gid = blockIdx.x * 256 + threadIdx.x;        // NT*OUT_FEAT/4 threads
    int i = gid >> 4;
    float4 n = ((const float4*)g_num)[gid];
    float inv = 1.f / fmaxf(g_den[i], 1e-30f);
    float v0 = n.x * inv, v1 = n.y * inv, v2 = n.z * inv, v3 = n.w * inv;
    float4 o;
    o.x = v0 > 0.f ? v0 : expm1f(v0);
    o.y = v1 > 0.f ? v1 : expm1f(v1);
    o.z = v2 > 0.f ? v2 : expm1f(v2);
    o.w = v3 > 0.f ? v3 : expm1f(v3);
    ((float4*)out)[gid] = o;
}

// =========================================================================
extern "C" void kernel_launch(void* const* d_in, const int* in_sizes, int n_in,
                              void* d_out, int out_size) {
    const float* x   = (const float*)d_in[0];
    const int*   adj = (const int*)d_in[1];
    const float* W   = (const float*)d_in[2];
    const float* a   = (const float*)d_in[3];
    float* out = (float*)d_out;

    cudaFuncSetAttribute(prep_kernel, cudaFuncAttributeMaxDynamicSharedMemorySize,
                         PREP_SMEM);
    cudaFuncSetAttribute(attn_kernel, cudaFuncAttributeMaxDynamicSharedMemorySize,
                         ATTN_SMEM);

    zero_kernel<<<(NT * OUT_FEAT) / 4 / 256, 256>>>();
    prep_kernel<<<NT / 32, 512, PREP_SMEM>>>(x, W, a);
    attn_kernel<<<WORKERS, 256, ATTN_SMEM>>>(adj);
    finalize_kernel<<<(NT * OUT_FEAT) / 4 / 256, 256>>>(out);
}

// round 13
// speedup vs baseline: 1.0004x; 1.0004x over previous
#include <cuda_runtime.h>
#include <cuda_fp16.h>
#include <cstdint>
#include <cstddef>

// ============================================================
// GAT attention head, N=8192, IN_F=128, OUT_F=64
//  h = X@W ; e = LeakyReLU(fs_i + fd_j) masked by adj ; softmax ; P@h ; elu
//
// exp(LR(fs+fd)) = max(E_i*E_j, G_i*G_j) -> no exp in N^2 loop.
// Fixed-max softmax -> single pass; fp16 P/h via mma.sync.m16n8k16.
//
// PERSISTENT: 296 CTAs own static contiguous ranges of 8192 tiles
// (64 row-blocks x 128 j-tiles of 64) -> 98.9% utilization; flush by
// atomicAdd on row-block change. Warp tiling M=32 x j-split 2.
// ============================================================

#define NT 8192
#define IN_FEAT 128
#define OUT_FEAT 64
#define JTILE 64
#define TOTAL_TILES 8192
#define WORKERS 296
#define ADJROW 320               // 64*4 + 64 pad: LDS.128 conflict-free
#define HROW 160                 // 64*2 + 32 pad: LDS.64 conflict-free

#define ADJ_BYTES (128 * ADJROW)         // 40960
#define H_BYTES   (OUT_FEAT * HROW)      // 10240
#define EG_BYTES  (JTILE * 8)            // 512
#define OFF_ADJ(i) ((i) * ADJ_BYTES)
#define OFF_H(i)   (2 * ADJ_BYTES + (i) * H_BYTES)
#define OFF_EG(i)  (2 * ADJ_BYTES + 2 * H_BYTES + (i) * EG_BYTES)
#define ATTN_SMEM  (2 * ADJ_BYTES + 2 * H_BYTES + 2 * EG_BYTES)  // 103424

#define PREP_WS   0
#define PREP_XS   (IN_FEAT * OUT_FEAT * 4)            // 32768
#define PREP_HS   (PREP_XS + 16 * IN_FEAT * 4)        // 40960
#define HS_STRIDE 18
#define PREP_SMEM (PREP_HS + OUT_FEAT * HS_STRIDE * 2) // 43264

// ---------------- scratch (static device arrays; no allocation) ----------
__device__ __half g_ht[OUT_FEAT * NT];
__device__ float2 g_EGs[NT];
__device__ float2 g_EGd[NT];
__device__ float  g_num[NT * OUT_FEAT];
__device__ float  g_den[NT];

// ---------------- helpers ------------------------------------------------
__device__ __forceinline__ uint32_t smem_u32(const void* p) {
    uint32_t a;
    asm("{ .reg .u64 t; cvta.to.shared.u64 t, %1; cvt.u32.u64 %0, t; }"
        : "=r"(a) : "l"(p));
    return a;
}
__device__ __forceinline__ void cp16(uint32_t dst, const void* src) {
    asm volatile("cp.async.cg.shared.global [%0], [%1], 16;" :: "r"(dst), "l"(src));
}
__device__ __forceinline__ void cp8(uint32_t dst, const void* src) {
    asm volatile("cp.async.ca.shared.global [%0], [%1], 8;" :: "r"(dst), "l"(src));
}
#define CP_COMMIT() asm volatile("cp.async.commit_group;" ::: "memory")
#define CP_WAIT(n)  asm volatile("cp.async.wait_group %0;" :: "n"(n) : "memory")

__device__ __forceinline__ void mma16816(float* d, uint32_t a0, uint32_t a1,
                                         uint32_t a2, uint32_t a3,
                                         uint32_t b0, uint32_t b1) {
    asm volatile(
        "mma.sync.aligned.m16n8k16.row.col.f32.f16.f16.f32 "
        "{%0,%1,%2,%3}, {%4,%5,%6,%7}, {%8,%9}, {%0,%1,%2,%3};"
        : "+f"(d[0]), "+f"(d[1]), "+f"(d[2]), "+f"(d[3])
        : "r"(a0), "r"(a1), "r"(a2), "r"(a3), "r"(b0), "r"(b1));
}
__device__ __forceinline__ uint32_t packh2(float x, float y) {
    __half2 h = __floats2half2_rn(x, y);
    return *reinterpret_cast<uint32_t*>(&h);
}

// =========================================================================
// Kernel 1: zero accumulators + h = X@W ; EG tables ; h^T fp16 (coalesced).
// 512 blocks x 256 threads; 16 rows/block; warp owns 2 rows; smem 43 KB
// -> ~3.5 CTAs/SM.
// =========================================================================
__global__ void __launch_bounds__(256) prep_kernel(const float* __restrict__ x,
                                                   const float* __restrict__ W,
                                                   const float* __restrict__ a) {
    extern __shared__ __align__(16) char sm[];
    float*  Ws = (float*)(sm + PREP_WS);
    float*  xs = (float*)(sm + PREP_XS);
    __half* hs = (__half*)(sm + PREP_HS);   // [64 f][18]

    int tid = threadIdx.x;
    int i0 = blockIdx.x * 16;

    // ---- zero the atomic accumulators (replaces zero_kernel) ----
    {
        int gz = blockIdx.x * 256 + tid;            // 131072 threads
        float4 z = make_float4(0.f, 0.f, 0.f, 0.f);
        ((float4*)g_num)[gz] = z;                   // 131072 float4 = all of g_num
        if (gz < NT / 4) ((float4*)g_den)[gz] = z;
    }

    {
        const float4* W4 = (const float4*)W;
        float4* Ws4 = (float4*)Ws;
#pragma unroll
        for (int u = 0; u < 8; u++) Ws4[tid + u * 256] = W4[tid + u * 256];
        const float4* x4 = (const float4*)(x + (size_t)i0 * IN_FEAT);
        float4* xs4 = (float4*)xs;
#pragma unroll
        for (int u = 0; u < 2; u++) xs4[tid + u * 256] = x4[tid + u * 256];
    }
    __syncthreads();

    int w = tid >> 5, l = tid & 31;       // warp w: rows 2w, 2w+1
    float acc[2][2];
#pragma unroll
    for (int rr = 0; rr < 2; rr++) { acc[rr][0] = 0.f; acc[rr][1] = 0.f; }

#pragma unroll 4
    for (int k4 = 0; k4 < IN_FEAT; k4 += 4) {
        float2 wv[4];
#pragma unroll
        for (int kk = 0; kk < 4; kk++)
            wv[kk] = *(const float2*)&Ws[(k4 + kk) * OUT_FEAT + 2 * l];
#pragma unroll
        for (int rr = 0; rr < 2; rr++) {
            float4 xv = *(const float4*)&xs[(w * 2 + rr) * IN_FEAT + k4];
            acc[rr][0] = fmaf(xv.x, wv[0].x, acc[rr][0]);
            acc[rr][1] = fmaf(xv.x, wv[0].y, acc[rr][1]);
            acc[rr][0] = fmaf(xv.y, wv[1].x, acc[rr][0]);
            acc[rr][1] = fmaf(xv.y, wv[1].y, acc[rr][1]);
            acc[rr][0] = fmaf(xv.z, wv[2].x, acc[rr][0]);
            acc[rr][1] = fmaf(xv.z, wv[2].y, acc[rr][1]);
            acc[rr][0] = fmaf(xv.w, wv[3].x, acc[rr][0]);
            acc[rr][1] = fmaf(xv.w, wv[3].y, acc[rr][1]);
        }
    }

#pragma unroll
    for (int rr = 0; rr < 2; rr++) {
        int il = w * 2 + rr;
        hs[(2 * l) * HS_STRIDE + il]     = __float2half(acc[rr][0]);
        hs[(2 * l + 1) * HS_STRIDE + il] = __float2half(acc[rr][1]);
    }

    float a0 = a[2 * l], a1 = a[2 * l + 1];
    float a2 = a[OUT_FEAT + 2 * l], a3 = a[OUT_FEAT + 2 * l + 1];
#pragma unroll
    for (int rr = 0; rr < 2; rr++) {
        float s = acc[rr][0] * a0 + acc[rr][1] * a1;
        float d = acc[rr][0] * a2 + acc[rr][1] * a3;
#pragma unroll
        for (int off = 16; off; off >>= 1) {
            s += __shfl_xor_sync(0xFFFFFFFFu, s, off);
            d += __shfl_xor_sync(0xFFFFFFFFu, d, off);
        }
        if (l == 0) {
            int i = i0 + w * 2 + rr;
            g_EGs[i] = make_float2(expf(s), expf(0.2f * s));
            g_EGd[i] = make_float2(expf(d), expf(0.2f * d));
        }
    }
    __syncthreads();

    // coalesced writeout: 64 f-rows x 8 half2 chunks; 2 per thread
#pragma unroll
    for (int u = 0; u < 2; u++) {
        int id = tid + u * 256;
        int f = id >> 3, c = id & 7;
        uint32_t v = *(const uint32_t*)&hs[f * HS_STRIDE + 2 * c];
        *(uint32_t*)&g_ht[(size_t)f * NT + i0 + 2 * c] = v;
    }
}

// =========================================================================
// Kernel 2: persistent fused attention. 296 CTAs x 256 thr, 2 CTAs/SM.
// Warp = (row-group wg 0..3) x (j-half jh 0..1): 32 rows x 64 feats.
// =========================================================================
__global__ void __launch_bounds__(256, 2) attn_kernel(const int* __restrict__ adj) {
    extern __shared__ __align__(16) char sm[];
    uint32_t sb = smem_u32(sm);

    int tid = threadIdx.x, w = tid >> 5, lane = tid & 31;
    int wg = w >> 1, jh = w & 1;
    int r = lane >> 2, q = lane & 3;
    int cta = blockIdx.x;

    int t0 = (int)(((long long)cta * TOTAL_TILES) / WORKERS);
    int t1 = (int)(((long long)(cta + 1) * TOTAL_TILES) / WORKERS);

    float acc[2][8][4];
#pragma unroll
    for (int mt = 0; mt < 2; mt++)
#pragma unroll
        for (int nt = 0; nt < 8; nt++)
#pragma unroll
            for (int v = 0; v < 4; v++) acc[mt][nt][v] = 0.f;
    float ds[4] = {0.f, 0.f, 0.f, 0.f};

    auto issue_tile = [&](int buf, int t) {
        int i0t = (t >> 7) * 128;
        int j0t = (t & 127) * JTILE;
        uint32_t ab = sb + OFF_ADJ(buf);
        uint32_t hb = sb + OFF_H(buf);
        uint32_t eb = sb + OFF_EG(buf);
#pragma unroll
        for (int u = 0; u < 8; u++) {
            int id = tid + u * 256;
            int row = id >> 4, c = id & 15;
            cp16(ab + row * ADJROW + c * 16,
                 &adj[(size_t)(i0t + row) * NT + j0t + c * 4]);
        }
#pragma unroll
        for (int u = 0; u < 2; u++) {
            int id = tid + u * 256;
            int f = id >> 3, c = id & 7;
            cp16(hb + f * HROW + c * 16,
                 &g_ht[(size_t)f * NT + j0t + c * 8]);
        }
        if (tid < JTILE) cp8(eb + tid * 8, &g_EGd[j0t + tid]);
        CP_COMMIT();
    };

    int cur_rb = t0 >> 7;
    float2 egs[4];
#pragma unroll
    for (int m = 0; m < 4; m++) egs[m] = g_EGs[cur_rb * 128 + wg * 32 + m * 8 + r];

    auto flush = [&](int rb) {
#pragma unroll
        for (int mt = 0; mt < 2; mt++) {
            float d0 = ds[mt * 2], d1 = ds[mt * 2 + 1];
            d0 += __shfl_xor_sync(0xFFFFFFFFu, d0, 1);
            d0 += __shfl_xor_sync(0xFFFFFFFFu, d0, 2);
            d1 += __shfl_xor_sync(0xFFFFFFFFu, d1, 1);
            d1 += __shfl_xor_sync(0xFFFFFFFFu, d1, 2);
            int R = rb * 128 + wg * 32 + mt * 16 + r;
            if (q == 0) {
                atomicAdd(&g_den[R], d0);
                atomicAdd(&g_den[R + 8], d1);
            }
#pragma unroll
            for (int nt = 0; nt < 8; nt++) {
                int col = nt * 8 + q * 2;
                atomicAdd(&g_num[(size_t)R * OUT_FEAT + col],           acc[mt][nt][0]);
                atomicAdd(&g_num[(size_t)R * OUT_FEAT + col + 1],       acc[mt][nt][1]);
                atomicAdd(&g_num[(size_t)(R + 8) * OUT_FEAT + col],     acc[mt][nt][2]);
                atomicAdd(&g_num[(size_t)(R + 8) * OUT_FEAT + col + 1], acc[mt][nt][3]);
                acc[mt][nt][0] = acc[mt][nt][1] = acc[mt][nt][2] = acc[mt][nt][3] = 0.f;
            }
            ds[mt * 2] = 0.f; ds[mt * 2 + 1] = 0.f;
        }
    };

    issue_tile(t0 & 1, t0);

    for (int t = t0; t < t1; t++) {
        int b = t & 1;
        __syncthreads();
        if (t + 1 < t1) { issue_tile((t + 1) & 1, t + 1); CP_WAIT(1); }
        else            { CP_WAIT(0); }
        __syncthreads();

        int rb = t >> 7;
        if (rb != cur_rb) {
            flush(cur_rb);
            cur_rb = rb;
#pragma unroll
            for (int m = 0; m < 4; m++) egs[m] = g_EGs[rb * 128 + wg * 32 + m * 8 + r];
        }

        const char* ab = sm + OFF_ADJ(b);
        const char* hb = sm + OFF_H(b);
        const float2* eb = (const float2*)(sm + OFF_EG(b));

#pragma unroll
        for (int kk = 0; kk < 2; kk++) {
            int colb = jh * 128 + kk * 64 + q * 16;
            int rbase = wg * 32 + r;
            int4 av0 = *(const int4*)(ab + (rbase)      * ADJROW + colb);
            int4 av1 = *(const int4*)(ab + (rbase + 8)  * ADJROW + colb);
            int4 av2 = *(const int4*)(ab + (rbase + 16) * ADJROW + colb);
            int4 av3 = *(const int4*)(ab + (rbase + 24) * ADJROW + colb);
            int jloc = jh * 32 + kk * 16 + 4 * q;
            float4 egA = *(const float4*)&eb[jloc];
            float4 egB = *(const float4*)&eb[jloc + 2];

            float p[4][4];
            const int4* avp[4] = {&av0, &av1, &av2, &av3};
#pragma unroll
            for (int m = 0; m < 4; m++) {
                float E = egs[m].x, G = egs[m].y;
                p[m][0] = avp[m]->x ? fmaxf(E * egA.x, G * egA.y) : 0.f;
                p[m][1] = avp[m]->y ? fmaxf(E * egA.z, G * egA.w) : 0.f;
                p[m][2] = avp[m]->z ? fmaxf(E * egB.x, G * egB.y) : 0.f;
                p[m][3] = avp[m]->w ? fmaxf(E * egB.z, G * egB.w) : 0.f;
                ds[m] += (p[m][0] + p[m][1]) + (p[m][2] + p[m][3]);
            }

            uint32_t A0 = packh2(p[0][0], p[0][1]);
            uint32_t A1 = packh2(p[1][0], p[1][1]);
            uint32_t A2 = packh2(p[0][2], p[0][3]);
            uint32_t A3 = packh2(p[1][2], p[1][3]);
            uint32_t C0 = packh2(p[2][0], p[2][1]);
            uint32_t C1 = packh2(p[3][0], p[3][1]);
            uint32_t C2 = packh2(p[2][2], p[2][3]);
            uint32_t C3 = packh2(p[3][2], p[3][3]);

            int ko = jh * 64 + kk * 32 + q * 8;
#pragma unroll
            for (int nt = 0; nt < 8; nt++) {
                uint2 bb = *(const uint2*)(hb + (nt * 8 + r) * HROW + ko);
                mma16816(acc[0][nt], A0, A1, A2, A3, bb.x, bb.y);
                mma16816(acc[1][nt], C0, C1, C2, C3, bb.x, bb.y);
            }
        }
    }

    flush(cur_rb);
}

// =========================================================================
// Kernel 3: divide + elu, MLP=4 (two independent float4 chunks per thread)
// =========================================================================
#define FIN_HALF (NT * OUT_FEAT / 8)   // 65536 float4 per half
__global__ void __launch_bounds__(256) finalize_kernel(float* __restrict__ out) {
    int gid = blockIdx.x * 256 + threadIdx.x;        // 65536 threads
    const float4* num4 = (const float4*)g_num;
    float4* out4 = (float4*)out;

    float4 n0 = num4[gid];
    float4 n1 = num4[gid + FIN_HALF];
    float d0 = g_den[gid >> 4];
    float d1 = g_den[(gid + FIN_HALF) >> 4];

    float i0 = 1.f / fmaxf(d0, 1e-30f);
    float i1 = 1.f / fmaxf(d1, 1e-30f);
    float4 o0, o1;
    float v;
    v = n0.x * i0; o0.x = v > 0.f ? v : expm1f(v);
    v = n0.y * i0; o0.y = v > 0.f ? v : expm1f(v);
    v = n0.z * i0; o0.z = v > 0.f ? v : expm1f(v);
    v = n0.w * i0; o0.w = v > 0.f ? v : expm1f(v);
    v = n1.x * i1; o1.x = v > 0.f ? v : expm1f(v);
    v = n1.y * i1; o1.y = v > 0.f ? v : expm1f(v);
    v = n1.z * i1; o1.z = v > 0.f ? v : expm1f(v);
    v = n1.w * i1; o1.w = v > 0.f ? v : expm1f(v);

    out4[gid] = o0;
    out4[gid + FIN_HALF] = o1;
}

// =========================================================================
extern "C" void kernel_launch(void* const* d_in, const int* in_sizes, int n_in,
                              void* d_out, int out_size) {
    const float* x   = (const float*)d_in[0];
    const int*   adj = (const int*)d_in[1];
    const float* W   = (const float*)d_in[2];
    const float* a   = (const float*)d_in[3];
    float* out = (float*)d_out;

    cudaFuncSetAttribute(prep_kernel, cudaFuncAttributeMaxDynamicSharedMemorySize,
                         PREP_SMEM);
    cudaFuncSetAttribute(attn_kernel, cudaFuncAttributeMaxDynamicSharedMemorySize,
                         ATTN_SMEM);

    prep_kernel<<<NT / 16, 256, PREP_SMEM>>>(x, W, a);
    attn_kernel<<<WORKERS, 256, ATTN_SMEM>>>(adj);
    finalize_kernel<<<FIN_HALF / 256, 256>>>(out);
}

// round 14
// speedup vs baseline: 1.0536x; 1.0532x over previous
#include <cuda_runtime.h>
#include <cuda_fp16.h>
#include <cstdint>
#include <cstddef>

// ============================================================
// GAT attention head, N=8192, IN_F=128, OUT_F=64
//  h = X@W ; e = LeakyReLU(fs_i + fd_j) masked by adj ; softmax ; P@h ; elu
//
// exp(LR(fs+fd)) = max(E_i*E_j, G_i*G_j) -> no exp in N^2 loop.
// Fixed-max softmax -> single pass; fp16 P/h via mma.sync.m16n8k16.
//
// PERSISTENT: 296 CTAs own static contiguous ranges of 16384 tiles
// (64 row-blocks x 256 j-tiles of 32) -> ~98.9% utilization; flush by
// atomicAdd on row-block change. Warp = (row-group wg) x (j-half jh).
// 4-stage cp.async pipeline, prefetch distance 3, ONE barrier per tile:
//   wait_group(2) ; syncthreads ; issue(t+3) ; compute(t)
// adj stored with XOR-4 chunk swizzle (odd rows swap 64B halves) ->
// zero padding, LDS.128 conflict-free, 4 stages fit 2 CTAs/SM.
// ============================================================

#define NT 8192
#define IN_FEAT 128
#define OUT_FEAT 64
#define JTILE 32
#define TOTAL_TILES 16384            // 64 rb x 256 j-tiles
#define WORKERS 296
#define ADJROW 128                   // 32*4, no pad (swizzled)
#define HROW 96                      // 32*2 + 32 pad: LDS.64 conflict-free

#define ADJ_BYTES (128 * ADJROW)     // 16384
#define H_BYTES   (OUT_FEAT * HROW)  // 6144
#define EG_BYTES  (JTILE * 8)        // 256
#define NSTAGE 4
#define OFF_ADJ(i) ((i) * ADJ_BYTES)
#define OFF_H(i)   (NSTAGE * ADJ_BYTES + (i) * H_BYTES)
#define OFF_EG(i)  (NSTAGE * ADJ_BYTES + NSTAGE * H_BYTES + (i) * EG_BYTES)
#define ATTN_SMEM  (NSTAGE * (ADJ_BYTES + H_BYTES + EG_BYTES))   // 91136

#define PREP_WS   0
#define PREP_XS   (IN_FEAT * OUT_FEAT * 4)            // 32768
#define PREP_HS   (PREP_XS + 32 * IN_FEAT * 4)        // 49152
#define HS_STRIDE 34
#define PREP_SMEM (PREP_HS + OUT_FEAT * HS_STRIDE * 2) // 53504

// ---------------- scratch (static device arrays; no allocation) ----------
__device__ __half g_ht[OUT_FEAT * NT];
__device__ float2 g_EGs[NT];
__device__ float2 g_EGd[NT];
__device__ float  g_num[NT * OUT_FEAT];
__device__ float  g_den[NT];

// ---------------- helpers ------------------------------------------------
__device__ __forceinline__ uint32_t smem_u32(const void* p) {
    uint32_t a;
    asm("{ .reg .u64 t; cvta.to.shared.u64 t, %1; cvt.u32.u64 %0, t; }"
        : "=r"(a) : "l"(p));
    return a;
}
__device__ __forceinline__ void cp16(uint32_t dst, const void* src) {
    asm volatile("cp.async.cg.shared.global [%0], [%1], 16;" :: "r"(dst), "l"(src));
}
__device__ __forceinline__ void cp8(uint32_t dst, const void* src) {
    asm volatile("cp.async.ca.shared.global [%0], [%1], 8;" :: "r"(dst), "l"(src));
}
#define CP_COMMIT() asm volatile("cp.async.commit_group;" ::: "memory")
#define CP_WAIT(n)  asm volatile("cp.async.wait_group %0;" :: "n"(n) : "memory")

__device__ __forceinline__ void mma16816(float* d, uint32_t a0, uint32_t a1,
                                         uint32_t a2, uint32_t a3,
                                         uint32_t b0, uint32_t b1) {
    asm volatile(
        "mma.sync.aligned.m16n8k16.row.col.f32.f16.f16.f32 "
        "{%0,%1,%2,%3}, {%4,%5,%6,%7}, {%8,%9}, {%0,%1,%2,%3};"
        : "+f"(d[0]), "+f"(d[1]), "+f"(d[2]), "+f"(d[3])
        : "r"(a0), "r"(a1), "r"(a2), "r"(a3), "r"(b0), "r"(b1));
}
__device__ __forceinline__ uint32_t packh2(float x, float y) {
    __half2 h = __floats2half2_rn(x, y);
    return *reinterpret_cast<uint32_t*>(&h);
}

// =========================================================================
// Kernel 1: zero accumulators + h = X@W ; EG tables ; h^T fp16 (coalesced).
// 256 blocks x 512 threads; 32 rows/block; warp owns 2 rows (R10 shape,
// measured 11.7us).
// =========================================================================
__global__ void __launch_bounds__(512) prep_kernel(const float* __restrict__ x,
                                                   const float* __restrict__ W,
                                                   const float* __restrict__ a) {
    extern __shared__ __align__(16) char sm[];
    float*  Ws = (float*)(sm + PREP_WS);
    float*  xs = (float*)(sm + PREP_XS);
    __half* hs = (__half*)(sm + PREP_HS);

    int tid = threadIdx.x;
    int i0 = blockIdx.x * 32;

    // zero accumulators (replaces zero_kernel)
    {
        int gz = blockIdx.x * 512 + tid;            // 131072 threads total
        float4 z = make_float4(0.f, 0.f, 0.f, 0.f);
        ((float4*)g_num)[gz] = z;
        if (gz < NT / 4) ((float4*)g_den)[gz] = z;
    }

    {
        const float4* W4 = (const float4*)W;
        float4* Ws4 = (float4*)Ws;
#pragma unroll
        for (int u = 0; u < 4; u++) Ws4[tid + u * 512] = W4[tid + u * 512];
        const float4* x4 = (const float4*)(x + (size_t)i0 * IN_FEAT);
        float4* xs4 = (float4*)xs;
#pragma unroll
        for (int u = 0; u < 2; u++) xs4[tid + u * 512] = x4[tid + u * 512];
    }
    __syncthreads();

    int w = tid >> 5, l = tid & 31;
    float acc[2][2];
#pragma unroll
    for (int rr = 0; rr < 2; rr++) { acc[rr][0] = 0.f; acc[rr][1] = 0.f; }

#pragma unroll 4
    for (int k4 = 0; k4 < IN_FEAT; k4 += 4) {
        float2 wv[4];
#pragma unroll
        for (int kk = 0; kk < 4; kk++)
            wv[kk] = *(const float2*)&Ws[(k4 + kk) * OUT_FEAT + 2 * l];
#pragma unroll
        for (int rr = 0; rr < 2; rr++) {
            float4 xv = *(const float4*)&xs[(w * 2 + rr) * IN_FEAT + k4];
            acc[rr][0] = fmaf(xv.x, wv[0].x, acc[rr][0]);
            acc[rr][1] = fmaf(xv.x, wv[0].y, acc[rr][1]);
            acc[rr][0] = fmaf(xv.y, wv[1].x, acc[rr][0]);
            acc[rr][1] = fmaf(xv.y, wv[1].y, acc[rr][1]);
            acc[rr][0] = fmaf(xv.z, wv[2].x, acc[rr][0]);
            acc[rr][1] = fmaf(xv.z, wv[2].y, acc[rr][1]);
            acc[rr][0] = fmaf(xv.w, wv[3].x, acc[rr][0]);
            acc[rr][1] = fmaf(xv.w, wv[3].y, acc[rr][1]);
        }
    }

#pragma unroll
    for (int rr = 0; rr < 2; rr++) {
        int il = w * 2 + rr;
        hs[(2 * l) * HS_STRIDE + il]     = __float2half(acc[rr][0]);
        hs[(2 * l + 1) * HS_STRIDE + il] = __float2half(acc[rr][1]);
    }

    float a0 = a[2 * l], a1 = a[2 * l + 1];
    float a2 = a[OUT_FEAT + 2 * l], a3 = a[OUT_FEAT + 2 * l + 1];
#pragma unroll
    for (int rr = 0; rr < 2; rr++) {
        float s = acc[rr][0] * a0 + acc[rr][1] * a1;
        float d = acc[rr][0] * a2 + acc[rr][1] * a3;
#pragma unroll
        for (int off = 16; off; off >>= 1) {
            s += __shfl_xor_sync(0xFFFFFFFFu, s, off);
            d += __shfl_xor_sync(0xFFFFFFFFu, d, off);
        }
        if (l == 0) {
            int i = i0 + w * 2 + rr;
            g_EGs[i] = make_float2(expf(s), expf(0.2f * s));
            g_EGd[i] = make_float2(expf(d), expf(0.2f * d));
        }
    }
    __syncthreads();

#pragma unroll
    for (int u = 0; u < 2; u++) {
        int id = tid + u * 512;
        int f = id >> 4, c = id & 15;
        uint32_t v = *(const uint32_t*)&hs[f * HS_STRIDE + 2 * c];
        *(uint32_t*)&g_ht[(size_t)f * NT + i0 + 2 * c] = v;
    }
}

// =========================================================================
// Kernel 2: persistent fused attention, 4-stage pipeline, JTILE=32.
// 296 CTAs x 256 thr, 2 CTAs/SM. Warp = (wg 0..3) x (jh 0..1).
// =========================================================================
__global__ void __launch_bounds__(256, 2) attn_kernel(const int* __restrict__ adj) {
    extern __shared__ __align__(16) char sm[];
    uint32_t sb = smem_u32(sm);

    int tid = threadIdx.x, w = tid >> 5, lane = tid & 31;
    int wg = w >> 1, jh = w & 1;
    int r = lane >> 2, q = lane & 3;
    int cta = blockIdx.x;

    int t0 = (int)(((long long)cta * TOTAL_TILES) / WORKERS);
    int t1 = (int)(((long long)(cta + 1) * TOTAL_TILES) / WORKERS);

    float acc[2][8][4];
#pragma unroll
    for (int mt = 0; mt < 2; mt++)
#pragma unroll
        for (int nt = 0; nt < 8; nt++)
#pragma unroll
            for (int v = 0; v < 4; v++) acc[mt][nt][v] = 0.f;
    float ds[4] = {0.f, 0.f, 0.f, 0.f};

    // stage one tile: adj (128x32 int, XOR-4 swizzled) + H (64x32 fp16) + EG
    auto issue_tile = [&](int buf, int t) {
        int i0t = (t >> 8) * 128;
        int j0t = (t & 255) * JTILE;
        uint32_t ab = sb + OFF_ADJ(buf);
        uint32_t hb = sb + OFF_H(buf);
        uint32_t eb = sb + OFF_EG(buf);
#pragma unroll
        for (int u = 0; u < 4; u++) {           // adj: 1024 chunks / 256 thr
            int id = tid + u * 256;
            int row = id >> 3, c = id & 7;
            int cs = c ^ ((row & 1) << 2);      // swizzle: odd rows swap halves
            cp16(ab + row * ADJROW + cs * 16,
                 &adj[(size_t)(i0t + row) * NT + j0t + c * 4]);
        }
        {                                       // H: 256 chunks, 1/thread
            int f = tid >> 2, c = tid & 3;
            cp16(hb + f * HROW + c * 16,
                 &g_ht[(size_t)f * NT + j0t + c * 8]);
        }
        if (tid < JTILE) cp8(eb + tid * 8, &g_EGd[j0t + tid]);
        CP_COMMIT();
    };

    int cur_rb = t0 >> 8;
    float2 egs[4];
#pragma unroll
    for (int m = 0; m < 4; m++) egs[m] = g_EGs[cur_rb * 128 + wg * 32 + m * 8 + r];

    auto flush = [&](int rb) {
#pragma unroll
        for (int mt = 0; mt < 2; mt++) {
            float d0 = ds[mt * 2], d1 = ds[mt * 2 + 1];
            d0 += __shfl_xor_sync(0xFFFFFFFFu, d0, 1);
            d0 += __shfl_xor_sync(0xFFFFFFFFu, d0, 2);
            d1 += __shfl_xor_sync(0xFFFFFFFFu, d1, 1);
            d1 += __shfl_xor_sync(0xFFFFFFFFu, d1, 2);
            int R = rb * 128 + wg * 32 + mt * 16 + r;
            if (q == 0) {
                atomicAdd(&g_den[R], d0);
                atomicAdd(&g_den[R + 8], d1);
            }
#pragma unroll
            for (int nt = 0; nt < 8; nt++) {
                int col = nt * 8 + q * 2;
                atomicAdd(&g_num[(size_t)R * OUT_FEAT + col],           acc[mt][nt][0]);
                atomicAdd(&g_num[(size_t)R * OUT_FEAT + col + 1],       acc[mt][nt][1]);
                atomicAdd(&g_num[(size_t)(R + 8) * OUT_FEAT + col],     acc[mt][nt][2]);
                atomicAdd(&g_num[(size_t)(R + 8) * OUT_FEAT + col + 1], acc[mt][nt][3]);
                acc[mt][nt][0] = acc[mt][nt][1] = acc[mt][nt][2] = acc[mt][nt][3] = 0.f;
            }
            ds[mt * 2] = 0.f; ds[mt * 2 + 1] = 0.f;
        }
    };

    // prologue: prefetch up to 3 tiles
    int nissue = t1 - t0 < 3 ? t1 - t0 : 3;
    for (int k = 0; k < nissue; k++) issue_tile((t0 + k) & 3, t0 + k);

    // per-lane adj column (swizzle-aware, constant per lane)
    int colb = (((jh << 2) + q) ^ ((r & 1) << 2)) * 16;
    int jloc = jh * 16 + 4 * q;
    int ko = jh * 32 + q * 8;

    for (int t = t0; t < t1; t++) {
        int rem = t1 - 1 - t;                   // groups newer than mine
        if (rem >= 2)      { CP_WAIT(2); }
        else if (rem == 1) { CP_WAIT(1); }
        else               { CP_WAIT(0); }
        __syncthreads();                        // tile t visible; buf (t-1)&3 free
        if (t + 3 < t1) issue_tile((t + 3) & 3, t + 3);

        int rb = t >> 8;
        if (rb != cur_rb) {
            flush(cur_rb);
            cur_rb = rb;
#pragma unroll
            for (int m = 0; m < 4; m++) egs[m] = g_EGs[rb * 128 + wg * 32 + m * 8 + r];
        }

        int b = t & 3;
        const char* ab = sm + OFF_ADJ(b);
        const char* hb = sm + OFF_H(b);
        const float2* eb = (const float2*)(sm + OFF_EG(b));

        int rbase = wg * 32 + r;
        int4 av0 = *(const int4*)(ab + (rbase)      * ADJROW + colb);
        int4 av1 = *(const int4*)(ab + (rbase + 8)  * ADJROW + colb);
        int4 av2 = *(const int4*)(ab + (rbase + 16) * ADJROW + colb);
        int4 av3 = *(const int4*)(ab + (rbase + 24) * ADJROW + colb);
        float4 egA = *(const float4*)&eb[jloc];
        float4 egB = *(const float4*)&eb[jloc + 2];

        float p[4][4];
        const int4* avp[4] = {&av0, &av1, &av2, &av3};
#pragma unroll
        for (int m = 0; m < 4; m++) {
            float E = egs[m].x, G = egs[m].y;
            p[m][0] = avp[m]->x ? fmaxf(E * egA.x, G * egA.y) : 0.f;
            p[m][1] = avp[m]->y ? fmaxf(E * egA.z, G * egA.w) : 0.f;
            p[m][2] = avp[m]->z ? fmaxf(E * egB.x, G * egB.y) : 0.f;
            p[m][3] = avp[m]->w ? fmaxf(E * egB.z, G * egB.w) : 0.f;
            ds[m] += (p[m][0] + p[m][1]) + (p[m][2] + p[m][3]);
        }

        uint32_t A0 = packh2(p[0][0], p[0][1]);
        uint32_t A1 = packh2(p[1][0], p[1][1]);
        uint32_t A2 = packh2(p[0][2], p[0][3]);
        uint32_t A3 = packh2(p[1][2], p[1][3]);
        uint32_t C0 = packh2(p[2][0], p[2][1]);
        uint32_t C1 = packh2(p[3][0], p[3][1]);
        uint32_t C2 = packh2(p[2][2], p[2][3]);
        uint32_t C3 = packh2(p[3][2], p[3][3]);

#pragma unroll
        for (int nt = 0; nt < 8; nt++) {
            uint2 bb = *(const uint2*)(hb + (nt * 8 + r) * HROW + ko);
            mma16816(acc[0][nt], A0, A1, A2, A3, bb.x, bb.y);
            mma16816(acc[1][nt], C0, C1, C2, C3, bb.x, bb.y);
        }
    }

    flush(cur_rb);
}

// =========================================================================
// Kernel 3: divide + elu, MLP=4
// =========================================================================
#define FIN_HALF (NT * OUT_FEAT / 8)   // 65536 float4 per half
__global__ void __launch_bounds__(256) finalize_kernel(float* __restrict__ out) {
    int gid = blockIdx.x * 256 + threadIdx.x;
    const float4* num4 = (const float4*)g_num;
    float4* out4 = (float4*)out;

    float4 n0 = num4[gid];
    float4 n1 = num4[gid + FIN_HALF];
    float d0 = g_den[gid >> 4];
    float d1 = g_den[(gid + FIN_HALF) >> 4];

    float i0 = 1.f / fmaxf(d0, 1e-30f);
    float i1 = 1.f / fmaxf(d1, 1e-30f);
    float4 o0, o1;
    float v;
    v = n0.x * i0; o0.x = v > 0.f ? v : expm1f(v);
    v = n0.y * i0; o0.y = v > 0.f ? v : expm1f(v);
    v = n0.z * i0; o0.z = v > 0.f ? v : expm1f(v);
    v = n0.w * i0; o0.w = v > 0.f ? v : expm1f(v);
    v = n1.x * i1; o1.x = v > 0.f ? v : expm1f(v);
    v = n1.y * i1; o1.y = v > 0.f ? v : expm1f(v);
    v = n1.z * i1; o1.z = v > 0.f ? v : expm1f(v);
    v = n1.w * i1; o1.w = v > 0.f ? v : expm1f(v);

    out4[gid] = o0;
    out4[gid + FIN_HALF] = o1;
}

// =========================================================================
extern "C" void kernel_launch(void* const* d_in, const int* in_sizes, int n_in,
                              void* d_out, int out_size) {
    const float* x   = (const float*)d_in[0];
    const int*   adj = (const int*)d_in[1];
    const float* W   = (const float*)d_in[2];
    const float* a   = (const float*)d_in[3];
    float* out = (float*)d_out;

    cudaFuncSetAttribute(prep_kernel, cudaFuncAttributeMaxDynamicSharedMemorySize,
                         PREP_SMEM);
    cudaFuncSetAttribute(attn_kernel, cudaFuncAttributeMaxDynamicSharedMemorySize,
                         ATTN_SMEM);

    prep_kernel<<<NT / 32, 512, PREP_SMEM>>>(x, W, a);
    attn_kernel<<<WORKERS, 256, ATTN_SMEM>>>(adj);
    finalize_kernel<<<FIN_HALF / 256, 256>>>(out);
}

// round 15
// speedup vs baseline: 1.0833x; 1.0282x over previous
#include <cuda_runtime.h>
#include <cuda_fp16.h>
#include <cstdint>
#include <cstddef>

// ============================================================
// GAT attention head, N=8192, IN_F=128, OUT_F=64
//  h = X@W ; e = LeakyReLU(fs_i + fd_j) masked by adj ; softmax ; P@h ; elu
//
// exp(LR(fs+fd)) = max(E_i*E_j, G_i*G_j) -> no exp in N^2 loop.
// Fixed-max softmax -> single pass; fp16 P/h via mma.sync.m16n8k16.
//
// PERSISTENT: 444 CTAs (3/SM) own static contiguous ranges of 16384 tiles
// (64 row-blocks x 256 j-tiles of 32) -> 99.7% utilization; flush by
// atomicAdd on row-block change. Warp = 16 rows x 64 feats (M=16, lean
// registers -> 3 CTAs/SM). 3-stage cp.async pipeline, distance 2:
//   wait_group(1) ; syncthreads ; issue(t+2) ; compute(t)
// adj XOR-4 chunk swizzle (odd rows swap 64B halves): zero padding,
// LDS.128 conflict-free.
// ============================================================

#define NT 8192
#define IN_FEAT 128
#define OUT_FEAT 64
#define JTILE 32
#define TOTAL_TILES 16384            // 64 rb x 256 j-tiles
#define WORKERS 444                  // 3 per SM x 148
#define ADJROW 128                   // 32*4, no pad (swizzled)
#define HROW 96                      // 32*2 + 32 pad: LDS.64 conflict-free

#define ADJ_BYTES (128 * ADJROW)     // 16384
#define H_BYTES   (OUT_FEAT * HROW)  // 6144
#define EG_BYTES  (JTILE * 8)        // 256
#define NSTAGE 3
#define OFF_ADJ(i) ((i) * ADJ_BYTES)
#define OFF_H(i)   (NSTAGE * ADJ_BYTES + (i) * H_BYTES)
#define OFF_EG(i)  (NSTAGE * ADJ_BYTES + NSTAGE * H_BYTES + (i) * EG_BYTES)
#define ATTN_SMEM  (NSTAGE * (ADJ_BYTES + H_BYTES + EG_BYTES))   // 68352

#define PREP_WS   0
#define PREP_XS   (IN_FEAT * OUT_FEAT * 4)            // 32768
#define PREP_HS   (PREP_XS + 32 * IN_FEAT * 4)        // 49152
#define HS_STRIDE 34
#define PREP_SMEM (PREP_HS + OUT_FEAT * HS_STRIDE * 2) // 53504

// ---------------- scratch (static device arrays; no allocation) ----------
__device__ __half g_ht[OUT_FEAT * NT];
__device__ float2 g_EGs[NT];
__device__ float2 g_EGd[NT];
__device__ float  g_num[NT * OUT_FEAT];
__device__ float  g_den[NT];

// ---------------- helpers ------------------------------------------------
__device__ __forceinline__ uint32_t smem_u32(const void* p) {
    uint32_t a;
    asm("{ .reg .u64 t; cvta.to.shared.u64 t, %1; cvt.u32.u64 %0, t; }"
        : "=r"(a) : "l"(p));
    return a;
}
__device__ __forceinline__ void cp16(uint32_t dst, const void* src) {
    asm volatile("cp.async.cg.shared.global [%0], [%1], 16;" :: "r"(dst), "l"(src));
}
__device__ __forceinline__ void cp8(uint32_t dst, const void* src) {
    asm volatile("cp.async.ca.shared.global [%0], [%1], 8;" :: "r"(dst), "l"(src));
}
#define CP_COMMIT() asm volatile("cp.async.commit_group;" ::: "memory")
#define CP_WAIT(n)  asm volatile("cp.async.wait_group %0;" :: "n"(n) : "memory")

__device__ __forceinline__ void mma16816(float* d, uint32_t a0, uint32_t a1,
                                         uint32_t a2, uint32_t a3,
                                         uint32_t b0, uint32_t b1) {
    asm volatile(
        "mma.sync.aligned.m16n8k16.row.col.f32.f16.f16.f32 "
        "{%0,%1,%2,%3}, {%4,%5,%6,%7}, {%8,%9}, {%0,%1,%2,%3};"
        : "+f"(d[0]), "+f"(d[1]), "+f"(d[2]), "+f"(d[3])
        : "r"(a0), "r"(a1), "r"(a2), "r"(a3), "r"(b0), "r"(b1));
}
__device__ __forceinline__ uint32_t packh2(float x, float y) {
    __half2 h = __floats2half2_rn(x, y);
    return *reinterpret_cast<uint32_t*>(&h);
}

// =========================================================================
// Kernel 0: zero accumulators (separate; folding into prep measured -2.6us)
// =========================================================================
__global__ void __launch_bounds__(256) zero_kernel() {
    int gid = blockIdx.x * 256 + threadIdx.x;
    ((float4*)g_num)[gid] = make_float4(0.f, 0.f, 0.f, 0.f);
    if (gid < NT / 4)
        ((float4*)g_den)[gid] = make_float4(0.f, 0.f, 0.f, 0.f);
}

// =========================================================================
// Kernel 1: h = X@W ; EG tables ; h^T fp16 (coalesced via smem transpose).
// EXACT R9 shape (measured 11.07us): 256 blocks x 256 threads, 4 rows/warp.
// =========================================================================
__global__ void __launch_bounds__(256) prep_kernel(const float* __restrict__ x,
                                                   const float* __restrict__ W,
                                                   const float* __restrict__ a) {
    extern __shared__ __align__(16) char sm[];
    float*  Ws = (float*)(sm + PREP_WS);
    float*  xs = (float*)(sm + PREP_XS);
    __half* hs = (__half*)(sm + PREP_HS);   // [64 f][34]

    int tid = threadIdx.x;
    int i0 = blockIdx.x * 32;

    {
        const float4* W4 = (const float4*)W;
        float4* Ws4 = (float4*)Ws;
#pragma unroll
        for (int u = 0; u < 8; u++) Ws4[tid + u * 256] = W4[tid + u * 256];
        const float4* x4 = (const float4*)(x + (size_t)i0 * IN_FEAT);
        float4* xs4 = (float4*)xs;
#pragma unroll
        for (int u = 0; u < 4; u++) xs4[tid + u * 256] = x4[tid + u * 256];
    }
    __syncthreads();

    int w = tid >> 5, l = tid & 31;
    float acc[4][2];
#pragma unroll
    for (int rr = 0; rr < 4; rr++) { acc[rr][0] = 0.f; acc[rr][1] = 0.f; }

#pragma unroll 4
    for (int k4 = 0; k4 < IN_FEAT; k4 += 4) {
        float2 wv[4];
#pragma unroll
        for (int kk = 0; kk < 4; kk++)
            wv[kk] = *(const float2*)&Ws[(k4 + kk) * OUT_FEAT + 2 * l];
#pragma unroll
        for (int rr = 0; rr < 4; rr++) {
            float4 xv = *(const float4*)&xs[(w * 4 + rr) * IN_FEAT + k4];
            acc[rr][0] = fmaf(xv.x, wv[0].x, acc[rr][0]);
            acc[rr][1] = fmaf(xv.x, wv[0].y, acc[rr][1]);
            acc[rr][0] = fmaf(xv.y, wv[1].x, acc[rr][0]);
            acc[rr][1] = fmaf(xv.y, wv[1].y, acc[rr][1]);
            acc[rr][0] = fmaf(xv.z, wv[2].x, acc[rr][0]);
            acc[rr][1] = fmaf(xv.z, wv[2].y, acc[rr][1]);
            acc[rr][0] = fmaf(xv.w, wv[3].x, acc[rr][0]);
            acc[rr][1] = fmaf(xv.w, wv[3].y, acc[rr][1]);
        }
    }

#pragma unroll
    for (int rr = 0; rr < 4; rr++) {
        int il = w * 4 + rr;
        hs[(2 * l) * HS_STRIDE + il]     = __float2half(acc[rr][0]);
        hs[(2 * l + 1) * HS_STRIDE + il] = __float2half(acc[rr][1]);
    }

    float a0 = a[2 * l], a1 = a[2 * l + 1];
    float a2 = a[OUT_FEAT + 2 * l], a3 = a[OUT_FEAT + 2 * l + 1];
#pragma unroll
    for (int rr = 0; rr < 4; rr++) {
        float s = acc[rr][0] * a0 + acc[rr][1] * a1;
        float d = acc[rr][0] * a2 + acc[rr][1] * a3;
#pragma unroll
        for (int off = 16; off; off >>= 1) {
            s += __shfl_xor_sync(0xFFFFFFFFu, s, off);
            d += __shfl_xor_sync(0xFFFFFFFFu, d, off);
        }
        if (l == 0) {
            int i = i0 + w * 4 + rr;
            g_EGs[i] = make_float2(expf(s), expf(0.2f * s));
            g_EGd[i] = make_float2(expf(d), expf(0.2f * d));
        }
    }
    __syncthreads();

#pragma unroll
    for (int u = 0; u < 4; u++) {
        int id = tid + u * 256;
        int f = id >> 4, c = id & 15;
        uint32_t v = *(const uint32_t*)&hs[f * HS_STRIDE + 2 * c];
        *(uint32_t*)&g_ht[(size_t)f * NT + i0 + 2 * c] = v;
    }
}

// =========================================================================
// Kernel 2: persistent fused attention, 3-stage pipeline, 3 CTAs/SM.
// 444 CTAs x 256 thr. Warp w: rows w*16..w*16+15, all 32 j (2 kk steps).
// =========================================================================
__global__ void __launch_bounds__(256, 3) attn_kernel(const int* __restrict__ adj) {
    extern __shared__ __align__(16) char sm[];
    uint32_t sb = smem_u32(sm);

    int tid = threadIdx.x, w = tid >> 5, lane = tid & 31;
    int r = lane >> 2, q = lane & 3;
    int cta = blockIdx.x;

    int t0 = (int)(((long long)cta * TOTAL_TILES) / WORKERS);
    int t1 = (int)(((long long)(cta + 1) * TOTAL_TILES) / WORKERS);

    float acc[8][4];
#pragma unroll
    for (int nt = 0; nt < 8; nt++)
#pragma unroll
        for (int v = 0; v < 4; v++) acc[nt][v] = 0.f;
    float ds0 = 0.f, ds1 = 0.f;

    // stage one tile: adj (128x32 int, XOR-4 swizzled) + H (64x32 fp16) + EG
    auto issue_tile = [&](int buf, int t) {
        int i0t = (t >> 8) * 128;
        int j0t = (t & 255) * JTILE;
        uint32_t ab = sb + OFF_ADJ(buf);
        uint32_t hb = sb + OFF_H(buf);
        uint32_t eb = sb + OFF_EG(buf);
#pragma unroll
        for (int u = 0; u < 4; u++) {           // adj: 1024 chunks / 256 thr
            int id = tid + u * 256;
            int row = id >> 3, c = id & 7;
            int cs = c ^ ((row & 1) << 2);      // odd rows swap 64B halves
            cp16(ab + row * ADJROW + cs * 16,
                 &adj[(size_t)(i0t + row) * NT + j0t + c * 4]);
        }
        {                                       // H: 256 chunks, 1/thread
            int f = tid >> 2, c = tid & 3;
            cp16(hb + f * HROW + c * 16,
                 &g_ht[(size_t)f * NT + j0t + c * 8]);
        }
        if (tid < JTILE) cp8(eb + tid * 8, &g_EGd[j0t + tid]);
        CP_COMMIT();
    };

    int cur_rb = t0 >> 8;
    float2 egs0 = g_EGs[cur_rb * 128 + w * 16 + r];
    float2 egs1 = g_EGs[cur_rb * 128 + w * 16 + r + 8];

    auto flush = [&](int rb) {
        float d0 = ds0, d1 = ds1;
        d0 += __shfl_xor_sync(0xFFFFFFFFu, d0, 1);
        d0 += __shfl_xor_sync(0xFFFFFFFFu, d0, 2);
        d1 += __shfl_xor_sync(0xFFFFFFFFu, d1, 1);
        d1 += __shfl_xor_sync(0xFFFFFFFFu, d1, 2);
        int R = rb * 128 + w * 16 + r;
        if (q == 0) {
            atomicAdd(&g_den[R], d0);
            atomicAdd(&g_den[R + 8], d1);
        }
#pragma unroll
        for (int nt = 0; nt < 8; nt++) {
            int col = nt * 8 + q * 2;
            atomicAdd(&g_num[(size_t)R * OUT_FEAT + col],           acc[nt][0]);
            atomicAdd(&g_num[(size_t)R * OUT_FEAT + col + 1],       acc[nt][1]);
            atomicAdd(&g_num[(size_t)(R + 8) * OUT_FEAT + col],     acc[nt][2]);
            atomicAdd(&g_num[(size_t)(R + 8) * OUT_FEAT + col + 1], acc[nt][3]);
            acc[nt][0] = acc[nt][1] = acc[nt][2] = acc[nt][3] = 0.f;
        }
        ds0 = 0.f; ds1 = 0.f;
    };

    // prologue: prefetch up to 2 tiles
    int nissue = t1 - t0 < 2 ? t1 - t0 : 2;
    for (int k = 0; k < nissue; k++) issue_tile((t0 + k) % 3, t0 + k);

    for (int t = t0; t < t1; t++) {
        if (t + 1 < t1) { CP_WAIT(1); }
        else            { CP_WAIT(0); }
        __syncthreads();                        // tile t visible; (t-1)%3 free
        if (t + 2 < t1) issue_tile((t + 2) % 3, t + 2);

        int rb = t >> 8;
        if (rb != cur_rb) {
            flush(cur_rb);
            cur_rb = rb;
            egs0 = g_EGs[rb * 128 + w * 16 + r];
            egs1 = g_EGs[rb * 128 + w * 16 + r + 8];
        }

        int b = t % 3;
        const char* ab = sm + OFF_ADJ(b);
        const char* hb = sm + OFF_H(b);
        const float2* eb = (const float2*)(sm + OFF_EG(b));

#pragma unroll
        for (int kk = 0; kk < 2; kk++) {
            int c = kk * 4 + q;
            int cs = c ^ ((r & 1) << 2);        // rows r and r+8: same parity
            int colb = cs * 16;
            int4 avA = *(const int4*)(ab + (w * 16 + r) * ADJROW + colb);
            int4 avB = *(const int4*)(ab + (w * 16 + r + 8) * ADJROW + colb);
            int jloc = kk * 16 + 4 * q;
            float4 egA = *(const float4*)&eb[jloc];     // E,G: j, j+1
            float4 egB = *(const float4*)&eb[jloc + 2]; // E,G: j+2, j+3

            float p00 = avA.x ? fmaxf(egs0.x * egA.x, egs0.y * egA.y) : 0.f;
            float p01 = avA.y ? fmaxf(egs0.x * egA.z, egs0.y * egA.w) : 0.f;
            float p02 = avA.z ? fmaxf(egs0.x * egB.x, egs0.y * egB.y) : 0.f;
            float p03 = avA.w ? fmaxf(egs0.x * egB.z, egs0.y * egB.w) : 0.f;
            float p10 = avB.x ? fmaxf(egs1.x * egA.x, egs1.y * egA.y) : 0.f;
            float p11 = avB.y ? fmaxf(egs1.x * egA.z, egs1.y * egA.w) : 0.f;
            float p12 = avB.z ? fmaxf(egs1.x * egB.x, egs1.y * egB.y) : 0.f;
            float p13 = avB.w ? fmaxf(egs1.x * egB.z, egs1.y * egB.w) : 0.f;

            ds0 += (p00 + p01) + (p02 + p03);
            ds1 += (p10 + p11) + (p12 + p13);

            // sigma: a0=(k=2q,2q+1)->j=4q,4q+1 ; a2=(k=2q+8,2q+9)->j=4q+2,4q+3
            uint32_t A0 = packh2(p00, p01);
            uint32_t A1 = packh2(p10, p11);
            uint32_t A2 = packh2(p02, p03);
            uint32_t A3 = packh2(p12, p13);

            int ko = kk * 32 + q * 8;
#pragma unroll
            for (int nt = 0; nt < 8; nt++) {
                uint2 bb = *(const uint2*)(hb + (nt * 8 + r) * HROW + ko);
                mma16816(acc[nt], A0, A1, A2, A3, bb.x, bb.y);
            }
        }
    }

    flush(cur_rb);
}

// =========================================================================
// Kernel 3: divide + elu, MLP=4
// =========================================================================
#define FIN_HALF (NT * OUT_FEAT / 8)   // 65536 float4 per half
__global__ void __launch_bounds__(256) finalize_kernel(float* __restrict__ out) {
    int gid = blockIdx.x * 256 + threadIdx.x;
    const float4* num4 = (const float4*)g_num;
    float4* out4 = (float4*)out;

    float4 n0 = num4[gid];
    float4 n1 = num4[gid + FIN_HALF];
    float d0 = g_den[gid >> 4];
    float d1 = g_den[(gid + FIN_HALF) >> 4];

    float i0 = 1.f / fmaxf(d0, 1e-30f);
    float i1 = 1.f / fmaxf(d1, 1e-30f);
    float4 o0, o1;
    float v;
    v = n0.x * i0; o0.x = v > 0.f ? v : expm1f(v);
    v = n0.y * i0; o0.y = v > 0.f ? v : expm1f(v);
    v = n0.z * i0; o0.z = v > 0.f ? v : expm1f(v);
    v = n0.w * i0; o0.w = v > 0.f ? v : expm1f(v);
    v = n1.x * i1; o1.x = v > 0.f ? v : expm1f(v);
    v = n1.y * i1; o1.y = v > 0.f ? v : expm1f(v);
    v = n1.z * i1; o1.z = v > 0.f ? v : expm1f(v);
    v = n1.w * i1; o1.w = v > 0.f ? v : expm1f(v);

    out4[gid] = o0;
    out4[gid + FIN_HALF] = o1;
}

// =========================================================================
extern "C" void kernel_launch(void* const* d_in, const int* in_sizes, int n_in,
                              void* d_out, int out_size) {
    const float* x   = (const float*)d_in[0];
    const int*   adj = (const int*)d_in[1];
    const float* W   = (const float*)d_in[2];
    const float* a   = (const float*)d_in[3];
    float* out = (float*)d_out;

    cudaFuncSetAttribute(prep_kernel, cudaFuncAttributeMaxDynamicSharedMemorySize,
                         PREP_SMEM);
    cudaFuncSetAttribute(attn_kernel, cudaFuncAttributeMaxDynamicSharedMemorySize,
                         ATTN_SMEM);

    zero_kernel<<<(NT * OUT_FEAT) / 4 / 256, 256>>>();
    prep_kernel<<<NT / 32, 256, PREP_SMEM>>>(x, W, a);
    attn_kernel<<<WORKERS, 256, ATTN_SMEM>>>(adj);
    finalize_kernel<<<FIN_HALF / 256, 256>>>(out);
}